// round 12
// baseline (speedup 1.0000x reference)
#include <cuda_runtime.h>
#include <cuda_fp16.h>
#include <math.h>
#include <stdint.h>

#define NTOK 4096
#define CDIM 1024
#define NEXP 8
#define DFF  4096
#define CAP  1024
#define TSEQ 2048
#define BSZ  2

// tgemm4 (fp16): 128x128 tile, BK=32, 4 stages
#define A4_STAGE_B 10240
#define B4_STAGE_B 8704
#define B4_OFF_B   40960                 // 4 * A4_STAGE_B
#define SMEM4_BYTES (B4_OFF_B + 4 * B4_STAGE_B)   // 75776

__device__ __align__(16) __half g_h1h [NTOK * CDIM];
__device__ float g_qkv  [NTOK * 3 * CDIM];
__device__ __align__(16) __half g_attnh[NTOK * CDIM];
__device__ float g_x2   [NTOK * CDIM];
__device__ float g_h2   [NTOK * CDIM];
__device__ __align__(16) __half g_h2h [NTOK * CDIM];
__device__ float g_logits [NTOK * NEXP];
__device__ float g_nlogits[NTOK * NEXP];
__device__ int   g_sel  [NTOK];
__device__ float g_gate [NTOK * 2];
__device__ int   g_slot_idx [NEXP * CAP];
__device__ float g_slot_gate[NEXP * CAP];
__device__ __align__(16) __half g_zeroh[CDIM];
__device__ __align__(16) __half g_hidh [(size_t)NEXP * CAP * DFF];
__device__ float g_upd [NTOK * CDIM];
__device__ float g_ent;
__device__ __align__(16) __half2 g_wqkvh[512 * 3072];
__device__ __align__(16) __half2 g_wouth[512 * 1024];
__device__ __align__(16) __half2 g_w1h[(size_t)NEXP * 512 * DFF];
__device__ __align__(16) __half2 g_w2h[(size_t)NEXP * 2048 * CDIM];

__device__ __forceinline__ void mma_f16(float c[4], const uint32_t a[4], const uint32_t b[2]) {
    asm volatile("mma.sync.aligned.m16n8k16.row.col.f32.f16.f16.f32 "
        "{%0,%1,%2,%3},{%4,%5,%6,%7},{%8,%9},{%0,%1,%2,%3};"
        : "+f"(c[0]), "+f"(c[1]), "+f"(c[2]), "+f"(c[3])
        : "r"(a[0]), "r"(a[1]), "r"(a[2]), "r"(a[3]), "r"(b[0]), "r"(b[1]));
}
__device__ __forceinline__ uint32_t packh2(float a, float b) {
    __half2 h = __floats2half2_rn(a, b);
    return *(uint32_t*)&h;
}
__device__ __forceinline__ void ldsm_x4(uint32_t r[4], uint32_t saddr) {
    asm volatile("ldmatrix.sync.aligned.m8n8.x4.shared.b16 {%0,%1,%2,%3}, [%4];"
        : "=r"(r[0]), "=r"(r[1]), "=r"(r[2]), "=r"(r[3]) : "r"(saddr));
}

__global__ void zero_kernel() {
    size_t i = (size_t)blockIdx.x * blockDim.x + threadIdx.x;
    ((float4*)g_upd)[i] = make_float4(0.f, 0.f, 0.f, 0.f);
    if (i < CDIM / 8) ((float4*)g_zeroh)[i] = make_float4(0.f, 0.f, 0.f, 0.f);
    if (i == 0) g_ent = 0.f;
}

// pack fp32 [K][N] -> half2 [K/2][N], 4 columns/thread
__global__ __launch_bounds__(256) void convw_kernel(const float* __restrict__ src,
                                                    __half2* __restrict__ dst,
                                                    int K2, int N) {
    size_t z = blockIdx.z;
    src += z * (size_t)K2 * 2 * N;
    dst += z * (size_t)K2 * N;
    size_t i4 = (size_t)blockIdx.x * 256 + threadIdx.x;
    int n4 = N >> 2;
    int k2 = (int)(i4 / n4), n = (int)(i4 % n4) << 2;
    float4 r0 = *(const float4*)&src[(size_t)(2 * k2) * N + n];
    float4 r1 = *(const float4*)&src[(size_t)(2 * k2 + 1) * N + n];
    uint4 o;
    o.x = packh2(r0.x, r1.x); o.y = packh2(r0.y, r1.y);
    o.z = packh2(r0.z, r1.z); o.w = packh2(r0.w, r1.w);
    *(uint4*)&dst[(size_t)k2 * N + n] = o;
}

__global__ __launch_bounds__(256) void ln_kernel(const float* __restrict__ x,
                                                 const float* __restrict__ gam,
                                                 const float* __restrict__ bet,
                                                 float* __restrict__ out,
                                                 __half* __restrict__ outh) {
    __shared__ float red[8];
    __shared__ float s_mu, s_rs;
    int row = blockIdx.x, tid = threadIdx.x;
    const float* xr = x + (size_t)row * CDIM;
    float v[4]; float s = 0.f;
#pragma unroll
    for (int i = 0; i < 4; i++) { v[i] = xr[tid + i * 256]; s += v[i]; }
    for (int o = 16; o; o >>= 1) s += __shfl_xor_sync(~0u, s, o);
    if ((tid & 31) == 0) red[tid >> 5] = s;
    __syncthreads();
    if (tid < 8) {
        float t = red[tid];
        for (int o = 4; o; o >>= 1) t += __shfl_xor_sync(0xffu, t, o);
        if (tid == 0) s_mu = t * (1.f / CDIM);
    }
    __syncthreads();
    float mu = s_mu, s2 = 0.f;
#pragma unroll
    for (int i = 0; i < 4; i++) { float d = v[i] - mu; s2 += d * d; }
    for (int o = 16; o; o >>= 1) s2 += __shfl_xor_sync(~0u, s2, o);
    if ((tid & 31) == 0) red[tid >> 5] = s2;
    __syncthreads();
    if (tid < 8) {
        float t = red[tid];
        for (int o = 4; o; o >>= 1) t += __shfl_xor_sync(0xffu, t, o);
        if (tid == 0) s_rs = rsqrtf(t * (1.f / CDIM) + 1e-5f);
    }
    __syncthreads();
    float rs = s_rs;
#pragma unroll
    for (int i = 0; i < 4; i++) {
        int c = tid + i * 256;
        float val = (v[i] - mu) * rs * gam[c] + bet[c];
        if (out)  out[(size_t)row * CDIM + c] = val;
        if (outh) outh[(size_t)row * CDIM + c] = __float2half(val);
    }
}

// fp16 HMMA GEMM: 128x128 tile, BK=32, 4-stage cp.async (depth 3), ldmatrix A-frags.
template <int EPI, bool GATHER, bool OUTH>
__global__ __launch_bounds__(256, 2) void tgemm4_kernel(
    const __half* __restrict__ A, const __half2* __restrict__ Bh, void* __restrict__ Cout,
    int M, int N, int K,
    const float* __restrict__ bias, const float* __restrict__ res,
    const int* __restrict__ sidx, const float* __restrict__ sgate,
    float* __restrict__ scat, const __half* __restrict__ zrow,
    size_t sA, size_t sB, size_t sC, int sBias)
{
    extern __shared__ float dsm[];
    __shared__ const __half* arow[128];

    const int z = blockIdx.z;
    const __half* Az = GATHER ? A : (A + (size_t)z * sA);
    const __half2* Bz = Bh + (size_t)z * sB;
    const float* bz = bias ? (bias + (size_t)z * sBias) : nullptr;

    const int tid = threadIdx.x;
    const int lane = tid & 31, wid = tid >> 5;
    const int wr = wid >> 2, wc = wid & 3;
    const int tg = lane >> 2, tq = lane & 3;

    if (tid < 128) {
        const __half* p;
        if (GATHER) {
            int idx = sidx[z * M + blockIdx.y * 128 + tid];
            p = (idx >= 0) ? (Az + (size_t)idx * K) : zrow;
        } else p = Az + (size_t)(blockIdx.y * 128 + tid) * K;
        arow[tid] = p;
    }
    __syncthreads();

    const uint32_t sbase = (uint32_t)__cvta_generic_to_shared(dsm);
    const int bxn = blockIdx.x * 128;
    // ldmatrix A address (per thread): row within tile + 16B k-half select
    const uint32_t lrow = (uint32_t)(wr * 64 + (lane & 7) + ((lane >> 3) & 1) * 8);
    const uint32_t aoff = lrow * 80u + (uint32_t)((lane >> 4) * 16);

#define ISSUE4(st, k0)                                                         \
    do {                                                                       \
        _Pragma("unroll")                                                      \
        for (int j_ = 0; j_ < 2; j_++) {                                       \
            int c_ = tid + j_ * 256;                                           \
            int row_ = c_ >> 2, ch_ = c_ & 3;                                  \
            uint32_t d_ = sbase + (uint32_t)((st) * A4_STAGE_B + row_ * 80 + ch_ * 16); \
            asm volatile("cp.async.cg.shared.global [%0], [%1], 16;"           \
                         :: "r"(d_), "l"(arow[row_] + (k0) + ch_ * 8));        \
        }                                                                      \
        _Pragma("unroll")                                                      \
        for (int j_ = 0; j_ < 2; j_++) {                                       \
            int c_ = tid + j_ * 256;                                           \
            int k2_ = c_ >> 5, n4_ = c_ & 31;                                  \
            uint32_t d_ = sbase + (uint32_t)(B4_OFF_B + (st) * B4_STAGE_B + k2_ * 544 + n4_ * 16); \
            asm volatile("cp.async.cg.shared.global [%0], [%1], 16;"           \
                         :: "r"(d_), "l"(Bz + (size_t)((k0) / 2 + k2_) * N + bxn + n4_ * 4)); \
        }                                                                      \
    } while (0)

    float acc[4][4][4];
#pragma unroll
    for (int i = 0; i < 4; i++)
#pragma unroll
        for (int j = 0; j < 4; j++)
#pragma unroll
            for (int q = 0; q < 4; q++) acc[i][j][q] = 0.f;

    const int KT = K >> 5;
    ISSUE4(0, 0);
    asm volatile("cp.async.commit_group;");
    ISSUE4(1, 32);
    asm volatile("cp.async.commit_group;");
    ISSUE4(2, 64);
    asm volatile("cp.async.commit_group;");

    for (int it = 0; it < KT; it++) {
        asm volatile("cp.async.wait_group 2;");
        __syncthreads();
        if (it + 3 < KT) ISSUE4((it + 3) & 3, (it + 3) * 32);
        asm volatile("cp.async.commit_group;");

        const int st = it & 3;
        const uint32_t Asb = sbase + (uint32_t)(st * A4_STAGE_B);
        const char* Bsb = (const char*)dsm + B4_OFF_B + st * B4_STAGE_B;
#pragma unroll
        for (int c = 0; c < 2; c++) {
            uint32_t af[4][4], bf[4][2];
#pragma unroll
            for (int mi = 0; mi < 4; mi++)
                ldsm_x4(af[mi], Asb + aoff + (uint32_t)(mi * 1280 + c * 32));
#pragma unroll
            for (int ni = 0; ni < 4; ni++) {
                int n0 = wc * 32 + ni * 8 + tg;
                const char* pb = Bsb + (c * 8 + tq) * 544 + n0 * 4;
                bf[ni][0] = *(const uint32_t*)pb;
                bf[ni][1] = *(const uint32_t*)(pb + 4 * 544);
            }
#pragma unroll
            for (int mi = 0; mi < 4; mi++)
#pragma unroll
                for (int ni = 0; ni < 4; ni++)
                    mma_f16(acc[mi][ni], af[mi], bf[ni]);
        }
    }
#undef ISSUE4

#pragma unroll
    for (int mi = 0; mi < 4; mi++) {
        int r0 = blockIdx.y * 128 + wr * 64 + mi * 16 + tg;
        int r1 = r0 + 8;
#pragma unroll
        for (int ni = 0; ni < 4; ni++) {
            int cc = blockIdx.x * 128 + wc * 32 + ni * 8 + tq * 2;
            float v00 = acc[mi][ni][0], v01 = acc[mi][ni][1];
            float v10 = acc[mi][ni][2], v11 = acc[mi][ni][3];
            if (bz) {
                float b0v = bz[cc], b1v = bz[cc + 1];
                v00 += b0v; v01 += b1v; v10 += b0v; v11 += b1v;
            }
            if (EPI == 1) {
                v00 = fmaxf(v00, 0.f); v01 = fmaxf(v01, 0.f);
                v10 = fmaxf(v10, 0.f); v11 = fmaxf(v11, 0.f);
            }
            if (EPI == 2) {
                float2 e0 = *(const float2*)&res[(size_t)r0 * N + cc];
                float2 e1 = *(const float2*)&res[(size_t)r1 * N + cc];
                v00 += e0.x; v01 += e0.y; v10 += e1.x; v11 += e1.y;
            }
            if (EPI == 3) {
                int gs0 = z * M + r0, gs1 = z * M + r1;
                int i0 = sidx[gs0], i1 = sidx[gs1];
                if (i0 >= 0) {
                    float g = sgate[gs0];
                    atomicAdd(&scat[(size_t)i0 * N + cc],     g * v00);
                    atomicAdd(&scat[(size_t)i0 * N + cc + 1], g * v01);
                }
                if (i1 >= 0) {
                    float g = sgate[gs1];
                    atomicAdd(&scat[(size_t)i1 * N + cc],     g * v10);
                    atomicAdd(&scat[(size_t)i1 * N + cc + 1], g * v11);
                }
            } else if (OUTH) {
                __half* Ch = (__half*)Cout + (size_t)z * sC;
                *(__half2*)&Ch[(size_t)r0 * N + cc] = __floats2half2_rn(v00, v01);
                *(__half2*)&Ch[(size_t)r1 * N + cc] = __floats2half2_rn(v10, v11);
            } else {
                float* Cf = (float*)Cout + (size_t)z * sC;
                *(float2*)&Cf[(size_t)r0 * N + cc] = make_float2(v00, v01);
                *(float2*)&Cf[(size_t)r1 * N + cc] = make_float2(v10, v11);
            }
        }
    }
}

// fp16 flash attention (unchanged from R11)
__global__ __launch_bounds__(256, 2) void attn_f16_kernel(const float* __restrict__ qkv,
                                                          __half* __restrict__ aout) {
    __shared__ __half Ks[64][72];
    __shared__ __half Vt[64][72];
    const int bh = blockIdx.y, b = bh >> 4, h = bh & 15;
    const int tid = threadIdx.x, lane = tid & 31, w = tid >> 5;
    const int tg = lane >> 2, tq = lane & 3;
    const int q0 = blockIdx.x * 128 + w * 16;
    const float* qbase = qkv + (size_t)b * TSEQ * 3072 + h * 64;

    uint32_t qa[4][4];
    {
        const float* qr0 = qbase + (size_t)(q0 + tg) * 3072;
        const float* qr1 = qbase + (size_t)(q0 + tg + 8) * 3072;
#pragma unroll
        for (int kc = 0; kc < 4; kc++) {
            int d0 = kc * 16 + 2 * tq;
            qa[kc][0] = packh2(qr0[d0] * 0.125f,     qr0[d0 + 1] * 0.125f);
            qa[kc][1] = packh2(qr1[d0] * 0.125f,     qr1[d0 + 1] * 0.125f);
            qa[kc][2] = packh2(qr0[d0 + 8] * 0.125f, qr0[d0 + 9] * 0.125f);
            qa[kc][3] = packh2(qr1[d0 + 8] * 0.125f, qr1[d0 + 9] * 0.125f);
        }
    }
    float oacc[8][4];
#pragma unroll
    for (int dt = 0; dt < 8; dt++)
#pragma unroll
        for (int i = 0; i < 4; i++) oacc[dt][i] = 0.f;
    float m0 = -1e30f, m1 = -1e30f, l0 = 0.f, l1 = 0.f;
    const float* kbase = qbase + 1024;
    const float* vbase = qbase + 2048;

    for (int s0 = 0; s0 < TSEQ; s0 += 64) {
        __syncthreads();
        for (int i = tid; i < 64 * 16; i += 256) {
            int j = i >> 4, dv = (i & 15) << 2;
            float4 kv = *(const float4*)(kbase + (size_t)(s0 + j) * 3072 + dv);
            float4 vv = *(const float4*)(vbase + (size_t)(s0 + j) * 3072 + dv);
            *(__half2*)&Ks[j][dv]     = __floats2half2_rn(kv.x, kv.y);
            *(__half2*)&Ks[j][dv + 2] = __floats2half2_rn(kv.z, kv.w);
            Vt[dv][j]     = __float2half(vv.x);
            Vt[dv + 1][j] = __float2half(vv.y);
            Vt[dv + 2][j] = __float2half(vv.z);
            Vt[dv + 3][j] = __float2half(vv.w);
        }
        __syncthreads();

        float s[8][4];
#pragma unroll
        for (int nt = 0; nt < 8; nt++) {
            s[nt][0] = s[nt][1] = s[nt][2] = s[nt][3] = 0.f;
#pragma unroll
            for (int kc = 0; kc < 4; kc++) {
                uint32_t bb[2] = {*(const uint32_t*)&Ks[nt * 8 + tg][kc * 16 + 2 * tq],
                                  *(const uint32_t*)&Ks[nt * 8 + tg][kc * 16 + 8 + 2 * tq]};
                mma_f16(s[nt], qa[kc], bb);
            }
        }
        float rm0 = -1e30f, rm1 = -1e30f;
#pragma unroll
        for (int nt = 0; nt < 8; nt++) {
            rm0 = fmaxf(rm0, fmaxf(s[nt][0], s[nt][1]));
            rm1 = fmaxf(rm1, fmaxf(s[nt][2], s[nt][3]));
        }
        rm0 = fmaxf(rm0, __shfl_xor_sync(~0u, rm0, 1));
        rm0 = fmaxf(rm0, __shfl_xor_sync(~0u, rm0, 2));
        rm1 = fmaxf(rm1, __shfl_xor_sync(~0u, rm1, 1));
        rm1 = fmaxf(rm1, __shfl_xor_sync(~0u, rm1, 2));
        float mn0 = fmaxf(m0, rm0), mn1 = fmaxf(m1, rm1);
        float sc0 = __expf(m0 - mn0), sc1 = __expf(m1 - mn1);
        m0 = mn0; m1 = mn1;
        float rs0 = 0.f, rs1 = 0.f;
#pragma unroll
        for (int nt = 0; nt < 8; nt++) {
            s[nt][0] = __expf(s[nt][0] - mn0); s[nt][1] = __expf(s[nt][1] - mn0);
            s[nt][2] = __expf(s[nt][2] - mn1); s[nt][3] = __expf(s[nt][3] - mn1);
            rs0 += s[nt][0] + s[nt][1]; rs1 += s[nt][2] + s[nt][3];
        }
        rs0 += __shfl_xor_sync(~0u, rs0, 1); rs0 += __shfl_xor_sync(~0u, rs0, 2);
        rs1 += __shfl_xor_sync(~0u, rs1, 1); rs1 += __shfl_xor_sync(~0u, rs1, 2);
        l0 = l0 * sc0 + rs0; l1 = l1 * sc1 + rs1;
#pragma unroll
        for (int dt = 0; dt < 8; dt++) {
            oacc[dt][0] *= sc0; oacc[dt][1] *= sc0;
            oacc[dt][2] *= sc1; oacc[dt][3] *= sc1;
        }
#pragma unroll
        for (int c = 0; c < 4; c++) {
            uint32_t pa[4];
            pa[0] = packh2(s[2 * c][0],     s[2 * c][1]);
            pa[1] = packh2(s[2 * c][2],     s[2 * c][3]);
            pa[2] = packh2(s[2 * c + 1][0], s[2 * c + 1][1]);
            pa[3] = packh2(s[2 * c + 1][2], s[2 * c + 1][3]);
#pragma unroll
            for (int dt = 0; dt < 8; dt++) {
                uint32_t bb[2] = {*(const uint32_t*)&Vt[dt * 8 + tg][c * 16 + 2 * tq],
                                  *(const uint32_t*)&Vt[dt * 8 + tg][c * 16 + 8 + 2 * tq]};
                mma_f16(oacc[dt], pa, bb);
            }
        }
    }
    float inv0 = 1.f / l0, inv1 = 1.f / l1;
    __half* ab = aout + (size_t)b * TSEQ * CDIM;
    int t0 = q0 + tg, t1 = t0 + 8;
    int c0 = h * 64 + (t0 >> 5), r0b = (t0 & 31) * 64;
    int c1 = h * 64 + (t1 >> 5), r1b = (t1 & 31) * 64;
#pragma unroll
    for (int dt = 0; dt < 8; dt++) {
        int dd = dt * 8 + tq * 2;
        ab[(size_t)(r0b + dd) * CDIM + c0]     = __float2half(oacc[dt][0] * inv0);
        ab[(size_t)(r0b + dd + 1) * CDIM + c0] = __float2half(oacc[dt][1] * inv0);
        ab[(size_t)(r1b + dd) * CDIM + c1]     = __float2half(oacc[dt][2] * inv1);
        ab[(size_t)(r1b + dd + 1) * CDIM + c1] = __float2half(oacc[dt][3] * inv1);
    }
}

__global__ __launch_bounds__(256) void route_kernel(const float* __restrict__ wr,
                                                    const float* __restrict__ br,
                                                    const float* __restrict__ wn,
                                                    const float* __restrict__ bn) {
    int warp = threadIdx.x >> 5, lane = threadIdx.x & 31;
    int n = blockIdx.x * 8 + warp;
    const float* hp = g_h2 + (size_t)n * CDIM;
    float pr[8], pn[8];
#pragma unroll
    for (int e = 0; e < 8; e++) { pr[e] = 0.f; pn[e] = 0.f; }
    for (int c = lane; c < CDIM; c += 32) {
        float hv = hp[c];
#pragma unroll
        for (int e = 0; e < 8; e++) {
            pr[e] += hv * wr[c * 8 + e];
            pn[e] += hv * wn[c * 8 + e];
        }
    }
#pragma unroll
    for (int e = 0; e < 8; e++)
        for (int o = 16; o; o >>= 1) {
            pr[e] += __shfl_xor_sync(~0u, pr[e], o);
            pn[e] += __shfl_xor_sync(~0u, pn[e], o);
        }
    if (lane == 0)
#pragma unroll
        for (int e = 0; e < 8; e++) {
            g_logits[n * 8 + e]  = pr[e] + br[e];
            g_nlogits[n * 8 + e] = pn[e] + bn[e];
        }
}

__global__ __launch_bounds__(256) void route_post_kernel(const float* __restrict__ noise) {
    __shared__ float red[8];
    int n = blockIdx.x * blockDim.x + threadIdx.x;
    float noisy[8], mx = -1e30f;
#pragma unroll
    for (int e = 0; e < 8; e++) {
        float nl = g_nlogits[n * 8 + e];
        float sp = log1pf(expf(-fabsf(nl))) + fmaxf(nl, 0.f);
        float v = g_logits[n * 8 + e] + noise[n * 8 + e] * sp;
        noisy[e] = v; mx = fmaxf(mx, v);
    }
    float s = 0.f, p[8];
#pragma unroll
    for (int e = 0; e < 8; e++) { p[e] = expf(noisy[e] - mx); s += p[e]; }
    float inv = 1.f / s, ent = 0.f;
#pragma unroll
    for (int e = 0; e < 8; e++) { float pe = p[e] * inv; ent -= pe * logf(pe + 1e-8f); }
    int i0 = 0;
#pragma unroll
    for (int e = 1; e < 8; e++) if (noisy[e] > noisy[i0]) i0 = e;
    int i1 = (i0 == 0) ? 1 : 0;
#pragma unroll
    for (int e = 0; e < 8; e++) if (e != i0 && noisy[e] > noisy[i1]) i1 = e;
    float dgl = expf(noisy[i1] - noisy[i0]);
    float g0 = 1.f / (1.f + dgl), g1 = dgl * g0;
    g_sel[n] = i0 | (i1 << 8);
    g_gate[2 * n] = g0; g_gate[2 * n + 1] = g1;
    float es = ent;
    for (int o = 16; o; o >>= 1) es += __shfl_xor_sync(~0u, es, o);
    int lane = threadIdx.x & 31, wid = threadIdx.x >> 5;
    if (lane == 0) red[wid] = es;
    __syncthreads();
    if (threadIdx.x < 8) {
        float t = red[threadIdx.x];
        for (int o = 4; o; o >>= 1) t += __shfl_xor_sync(0xffu, t, o);
        if (threadIdx.x == 0) atomicAdd(&g_ent, t);
    }
}

__global__ void assign_kernel() {
    int lane = threadIdx.x;
    int cnt[8];
#pragma unroll
    for (int e = 0; e < 8; e++) cnt[e] = 0;
    unsigned lt = (1u << lane) - 1u;
    for (int n0 = 0; n0 < NTOK; n0 += 32) {
        int n = n0 + lane;
        int sel = g_sel[n];
        int e0 = sel & 255, e1 = (sel >> 8) & 255;
        float g0 = g_gate[2 * n], g1 = g_gate[2 * n + 1];
#pragma unroll
        for (int e = 0; e < 8; e++) {
            bool mt = (e0 == e) || (e1 == e);
            unsigned mask = __ballot_sync(~0u, mt);
            if (mt) {
                int r = cnt[e] + __popc(mask & lt);
                if (r < CAP) {
                    g_slot_idx[e * CAP + r]  = n;
                    g_slot_gate[e * CAP + r] = (e0 == e) ? g0 : g1;
                }
            }
            cnt[e] += __popc(mask);
        }
    }
#pragma unroll
    for (int e = 0; e < 8; e++)
        for (int r = cnt[e] + lane; r < CAP; r += 32) {
            g_slot_idx[e * CAP + r]  = -1;
            g_slot_gate[e * CAP + r] = 0.f;
        }
}

__global__ void final_kernel(float* __restrict__ out, int out_size) {
    int i = blockIdx.x * blockDim.x + threadIdx.x;
    if (i < NTOK * CDIM) out[i] = g_x2[i] + g_upd[i];
    else if (i < out_size) out[i] = g_ent * (1.f / NTOK);
}

static void* symp(const void* s) { void* p = nullptr; cudaGetSymbolAddress(&p, s); return p; }

extern "C" void kernel_launch(void* const* d_in, const int* in_sizes, int n_in,
                              void* d_out, int out_size) {
    const float* x       = (const float*)d_in[0];
    const float* noise   = (const float*)d_in[1];
    const float* gamma1  = (const float*)d_in[2];
    const float* beta1   = (const float*)d_in[3];
    const float* gamma2  = (const float*)d_in[4];
    const float* beta2   = (const float*)d_in[5];
    const float* w_qkv   = (const float*)d_in[6];
    const float* w_out   = (const float*)d_in[7];
    const float* w_route = (const float*)d_in[8];
    const float* b_route = (const float*)d_in[9];
    const float* w_noise = (const float*)d_in[10];
    const float* b_noise = (const float*)d_in[11];
    const float* w1      = (const float*)d_in[12];
    const float* b1      = (const float*)d_in[13];
    const float* w2      = (const float*)d_in[14];
    const float* b2      = (const float*)d_in[15];
    float* out = (float*)d_out;

    __half*  p_h1h   = (__half*)symp(g_h1h);
    float*   p_qkv   = (float*)symp(g_qkv);
    __half*  p_attnh = (__half*)symp(g_attnh);
    float*   p_x2    = (float*)symp(g_x2);
    float*   p_h2    = (float*)symp(g_h2);
    __half*  p_h2h   = (__half*)symp(g_h2h);
    __half*  p_hidh  = (__half*)symp(g_hidh);
    float*   p_upd   = (float*)symp(g_upd);
    __half*  p_zeroh = (__half*)symp(g_zeroh);
    __half2* p_wqkvh = (__half2*)symp(g_wqkvh);
    __half2* p_wouth = (__half2*)symp(g_wouth);
    __half2* p_w1h   = (__half2*)symp(g_w1h);
    __half2* p_w2h   = (__half2*)symp(g_w2h);
    int*     p_sidx  = (int*)symp(g_slot_idx);
    float*   p_sg    = (float*)symp(g_slot_gate);

    static int smem_set = 0;
    if (!smem_set) {
        cudaFuncSetAttribute(tgemm4_kernel<0, false, false>, cudaFuncAttributeMaxDynamicSharedMemorySize, SMEM4_BYTES);
        cudaFuncSetAttribute(tgemm4_kernel<2, false, false>, cudaFuncAttributeMaxDynamicSharedMemorySize, SMEM4_BYTES);
        cudaFuncSetAttribute(tgemm4_kernel<1, true,  true >, cudaFuncAttributeMaxDynamicSharedMemorySize, SMEM4_BYTES);
        cudaFuncSetAttribute(tgemm4_kernel<3, false, false>, cudaFuncAttributeMaxDynamicSharedMemorySize, SMEM4_BYTES);
        smem_set = 1;
    }

    zero_kernel<<<NTOK * CDIM / 4 / 256, 256>>>();
    convw_kernel<<<dim3(512 * 3072 / 4 / 256, 1, 1), 256>>>(w_qkv, p_wqkvh, 512, 3072);
    convw_kernel<<<dim3(512 * 1024 / 4 / 256, 1, 1), 256>>>(w_out, p_wouth, 512, 1024);
    convw_kernel<<<dim3(512 * DFF / 4 / 256, 1, NEXP), 256>>>(w1, p_w1h, 512, DFF);
    convw_kernel<<<dim3(2048 * CDIM / 4 / 256, 1, NEXP), 256>>>(w2, p_w2h, 2048, CDIM);

    ln_kernel<<<NTOK, 256>>>(x, gamma1, beta1, nullptr, p_h1h);
    tgemm4_kernel<0, false, false><<<dim3(3072 / 128, 4096 / 128, 1), 256, SMEM4_BYTES>>>(
        p_h1h, p_wqkvh, p_qkv, 4096, 3072, 1024,
        nullptr, nullptr, nullptr, nullptr, nullptr, p_zeroh, 0, 0, 0, 0);
    attn_f16_kernel<<<dim3(TSEQ / 128, BSZ * 16), 256>>>(p_qkv, p_attnh);
    tgemm4_kernel<2, false, false><<<dim3(1024 / 128, 4096 / 128, 1), 256, SMEM4_BYTES>>>(
        p_attnh, p_wouth, p_x2, 4096, 1024, 1024,
        nullptr, x, nullptr, nullptr, nullptr, p_zeroh, 0, 0, 0, 0);
    ln_kernel<<<NTOK, 256>>>(p_x2, gamma2, beta2, p_h2, p_h2h);
    route_kernel<<<NTOK / 8, 256>>>(w_route, b_route, w_noise, b_noise);
    route_post_kernel<<<NTOK / 256, 256>>>(noise);
    assign_kernel<<<1, 32>>>();
    tgemm4_kernel<1, true, true><<<dim3(DFF / 128, 1024 / 128, NEXP), 256, SMEM4_BYTES>>>(
        p_h2h, p_w1h, p_hidh, 1024, DFF, 1024,
        b1, nullptr, p_sidx, nullptr, nullptr, p_zeroh,
        0, (size_t)512 * DFF, (size_t)CAP * DFF, DFF);
    tgemm4_kernel<3, false, false><<<dim3(1024 / 128, 1024 / 128, NEXP), 256, SMEM4_BYTES>>>(
        p_hidh, p_w2h, nullptr, 1024, 1024, 4096,
        b2, nullptr, p_sidx, p_sg, p_upd, p_zeroh,
        (size_t)CAP * DFF, (size_t)2048 * CDIM, 0, CDIM);
    final_kernel<<<(out_size + 255) / 256, 256>>>(out, out_size);
}

// round 13
// speedup vs baseline: 1.0403x; 1.0403x over previous
#include <cuda_runtime.h>
#include <cuda_fp16.h>
#include <math.h>
#include <stdint.h>

#define NTOK 4096
#define CDIM 1024
#define NEXP 8
#define DFF  4096
#define CAP  1024
#define TSEQ 2048
#define BSZ  2

// tgemm4 (fp16): 128x128 tile, BK=32, 3 stages
#define A4_STAGE_B 10240
#define B4_STAGE_B 8704
#define B4_OFF_B   30720
#define SMEM4_BYTES (B4_OFF_B + 3 * B4_STAGE_B)

__device__ __align__(16) __half g_h1h [NTOK * CDIM];
__device__ __align__(16) __half g_qkvh[NTOK * 3 * CDIM];
__device__ __align__(16) __half g_attnh[NTOK * CDIM];
__device__ float g_x2   [NTOK * CDIM];
__device__ float g_h2   [NTOK * CDIM];
__device__ __align__(16) __half g_h2h [NTOK * CDIM];
__device__ float g_logits [NTOK * NEXP];
__device__ float g_nlogits[NTOK * NEXP];
__device__ int   g_sel  [NTOK];
__device__ float g_gate [NTOK * 2];
__device__ int   g_slot_idx [NEXP * CAP];
__device__ int   g_tok_slot [NTOK * 2];
__device__ __align__(16) __half g_zeroh[CDIM];
__device__ __align__(16) __half g_hidh [(size_t)NEXP * CAP * DFF];
__device__ __align__(16) __half g_yo   [(size_t)NEXP * CAP * CDIM];
__device__ float g_ent;
__device__ __align__(16) __half2 g_wqkvh[512 * 3072];
__device__ __align__(16) __half2 g_wouth[512 * 1024];
__device__ __align__(16) __half2 g_w1h[(size_t)NEXP * 512 * DFF];
__device__ __align__(16) __half2 g_w2h[(size_t)NEXP * 2048 * CDIM];

__device__ __forceinline__ void mma_f16(float c[4], const uint32_t a[4], const uint32_t b[2]) {
    asm volatile("mma.sync.aligned.m16n8k16.row.col.f32.f16.f16.f32 "
        "{%0,%1,%2,%3},{%4,%5,%6,%7},{%8,%9},{%0,%1,%2,%3};"
        : "+f"(c[0]), "+f"(c[1]), "+f"(c[2]), "+f"(c[3])
        : "r"(a[0]), "r"(a[1]), "r"(a[2]), "r"(a[3]), "r"(b[0]), "r"(b[1]));
}
__device__ __forceinline__ uint32_t packh2(float a, float b) {
    __half2 h = __floats2half2_rn(a, b);
    return *(uint32_t*)&h;
}

__global__ void zero_kernel() {
    int tid = threadIdx.x;
    ((uint2*)g_zeroh)[tid] = make_uint2(0u, 0u);
    if (tid == 0) g_ent = 0.f;
}

// pack fp32 [K][N] -> half2 [K/2][N], 4 columns/thread
__global__ __launch_bounds__(256) void convw_kernel(const float* __restrict__ src,
                                                    __half2* __restrict__ dst,
                                                    int K2, int N) {
    size_t z = blockIdx.z;
    src += z * (size_t)K2 * 2 * N;
    dst += z * (size_t)K2 * N;
    size_t i4 = (size_t)blockIdx.x * 256 + threadIdx.x;
    int n4 = N >> 2;
    int k2 = (int)(i4 / n4), n = (int)(i4 % n4) << 2;
    float4 r0 = *(const float4*)&src[(size_t)(2 * k2) * N + n];
    float4 r1 = *(const float4*)&src[(size_t)(2 * k2 + 1) * N + n];
    uint4 o;
    o.x = packh2(r0.x, r1.x); o.y = packh2(r0.y, r1.y);
    o.z = packh2(r0.z, r1.z); o.w = packh2(r0.w, r1.w);
    *(uint4*)&dst[(size_t)k2 * N + n] = o;
}

__global__ __launch_bounds__(256) void ln_kernel(const float* __restrict__ x,
                                                 const float* __restrict__ gam,
                                                 const float* __restrict__ bet,
                                                 float* __restrict__ out,
                                                 __half* __restrict__ outh) {
    __shared__ float red[8];
    __shared__ float s_mu, s_rs;
    int row = blockIdx.x, tid = threadIdx.x;
    const float* xr = x + (size_t)row * CDIM;
    float v[4]; float s = 0.f;
#pragma unroll
    for (int i = 0; i < 4; i++) { v[i] = xr[tid + i * 256]; s += v[i]; }
    for (int o = 16; o; o >>= 1) s += __shfl_xor_sync(~0u, s, o);
    if ((tid & 31) == 0) red[tid >> 5] = s;
    __syncthreads();
    if (tid < 8) {
        float t = red[tid];
        for (int o = 4; o; o >>= 1) t += __shfl_xor_sync(0xffu, t, o);
        if (tid == 0) s_mu = t * (1.f / CDIM);
    }
    __syncthreads();
    float mu = s_mu, s2 = 0.f;
#pragma unroll
    for (int i = 0; i < 4; i++) { float d = v[i] - mu; s2 += d * d; }
    for (int o = 16; o; o >>= 1) s2 += __shfl_xor_sync(~0u, s2, o);
    if ((tid & 31) == 0) red[tid >> 5] = s2;
    __syncthreads();
    if (tid < 8) {
        float t = red[tid];
        for (int o = 4; o; o >>= 1) t += __shfl_xor_sync(0xffu, t, o);
        if (tid == 0) s_rs = rsqrtf(t * (1.f / CDIM) + 1e-5f);
    }
    __syncthreads();
    float rs = s_rs;
#pragma unroll
    for (int i = 0; i < 4; i++) {
        int c = tid + i * 256;
        float val = (v[i] - mu) * rs * gam[c] + bet[c];
        if (out)  out[(size_t)row * CDIM + c] = val;
        if (outh) outh[(size_t)row * CDIM + c] = __float2half(val);
    }
}

// fp16 HMMA GEMM: 128x128 tile, BK=32, 3-stage cp.async, 2 CTAs/SM.
// EPI: 0 store(+bias), 1 relu(+bias), 2 store+residual. OUTH: half output.
template <int EPI, bool GATHER, bool OUTH>
__global__ __launch_bounds__(256, 2) void tgemm4_kernel(
    const __half* __restrict__ A, const __half2* __restrict__ Bh, void* __restrict__ Cout,
    int M, int N, int K,
    const float* __restrict__ bias, const float* __restrict__ res,
    const int* __restrict__ sidx, const __half* __restrict__ zrow,
    size_t sA, size_t sB, size_t sC, int sBias)
{
    extern __shared__ float dsm[];
    __shared__ const __half* arow[128];

    const int z = blockIdx.z;
    const __half* Az = GATHER ? A : (A + (size_t)z * sA);
    const __half2* Bz = Bh + (size_t)z * sB;
    const float* bz = bias ? (bias + (size_t)z * sBias) : nullptr;

    const int tid = threadIdx.x;
    const int lane = tid & 31, wid = tid >> 5;
    const int wr = wid >> 2, wc = wid & 3;
    const int tg = lane >> 2, tq = lane & 3;

    if (tid < 128) {
        const __half* p;
        if (GATHER) {
            int idx = sidx[z * M + blockIdx.y * 128 + tid];
            p = (idx >= 0) ? (Az + (size_t)idx * K) : zrow;
        } else p = Az + (size_t)(blockIdx.y * 128 + tid) * K;
        arow[tid] = p;
    }
    __syncthreads();

    const uint32_t sbase = (uint32_t)__cvta_generic_to_shared(dsm);
    const int bxn = blockIdx.x * 128;

#define ISSUE4(st, k0)                                                         \
    do {                                                                       \
        _Pragma("unroll")                                                      \
        for (int j_ = 0; j_ < 2; j_++) {                                       \
            int c_ = tid + j_ * 256;                                           \
            int row_ = c_ >> 2, ch_ = c_ & 3;                                  \
            uint32_t d_ = sbase + (uint32_t)((st) * A4_STAGE_B + row_ * 80 + ch_ * 16); \
            asm volatile("cp.async.cg.shared.global [%0], [%1], 16;"           \
                         :: "r"(d_), "l"(arow[row_] + (k0) + ch_ * 8));        \
        }                                                                      \
        _Pragma("unroll")                                                      \
        for (int j_ = 0; j_ < 2; j_++) {                                       \
            int c_ = tid + j_ * 256;                                           \
            int k2_ = c_ >> 5, n4_ = c_ & 31;                                  \
            uint32_t d_ = sbase + (uint32_t)(B4_OFF_B + (st) * B4_STAGE_B + k2_ * 544 + n4_ * 16); \
            asm volatile("cp.async.cg.shared.global [%0], [%1], 16;"           \
                         :: "r"(d_), "l"(Bz + (size_t)((k0) / 2 + k2_) * N + bxn + n4_ * 4)); \
        }                                                                      \
    } while (0)

    float acc[4][4][4];
#pragma unroll
    for (int i = 0; i < 4; i++)
#pragma unroll
        for (int j = 0; j < 4; j++)
#pragma unroll
            for (int q = 0; q < 4; q++) acc[i][j][q] = 0.f;

    const int KT = K >> 5;
    ISSUE4(0, 0);
    asm volatile("cp.async.commit_group;");
    ISSUE4(1, 32);
    asm volatile("cp.async.commit_group;");

    for (int it = 0; it < KT; it++) {
        asm volatile("cp.async.wait_group 1;");
        __syncthreads();
        if (it + 2 < KT) ISSUE4((it + 2) % 3, (it + 2) * 32);
        asm volatile("cp.async.commit_group;");

        const int st = it % 3;
        const char* Asb = (const char*)dsm + st * A4_STAGE_B;
        const char* Bsb = (const char*)dsm + B4_OFF_B + st * B4_STAGE_B;
#pragma unroll
        for (int c = 0; c < 2; c++) {
            uint32_t af[4][4], bf[4][2];
#pragma unroll
            for (int mi = 0; mi < 4; mi++) {
                int m0 = wr * 64 + mi * 16 + tg;
                const char* p0 = Asb + m0 * 80 + c * 32 + tq * 4;
                const char* p1 = Asb + (m0 + 8) * 80 + c * 32 + tq * 4;
                af[mi][0] = *(const uint32_t*)p0;
                af[mi][1] = *(const uint32_t*)p1;
                af[mi][2] = *(const uint32_t*)(p0 + 16);
                af[mi][3] = *(const uint32_t*)(p1 + 16);
            }
#pragma unroll
            for (int ni = 0; ni < 4; ni++) {
                int n0 = wc * 32 + ni * 8 + tg;
                const char* pb = Bsb + (c * 8 + tq) * 544 + n0 * 4;
                bf[ni][0] = *(const uint32_t*)pb;
                bf[ni][1] = *(const uint32_t*)(pb + 4 * 544);
            }
#pragma unroll
            for (int mi = 0; mi < 4; mi++)
#pragma unroll
                for (int ni = 0; ni < 4; ni++)
                    mma_f16(acc[mi][ni], af[mi], bf[ni]);
        }
    }
#undef ISSUE4

#pragma unroll
    for (int mi = 0; mi < 4; mi++) {
        int r0 = blockIdx.y * 128 + wr * 64 + mi * 16 + tg;
        int r1 = r0 + 8;
#pragma unroll
        for (int ni = 0; ni < 4; ni++) {
            int cc = blockIdx.x * 128 + wc * 32 + ni * 8 + tq * 2;
            float v00 = acc[mi][ni][0], v01 = acc[mi][ni][1];
            float v10 = acc[mi][ni][2], v11 = acc[mi][ni][3];
            if (bz) {
                float b0v = bz[cc], b1v = bz[cc + 1];
                v00 += b0v; v01 += b1v; v10 += b0v; v11 += b1v;
            }
            if (EPI == 1) {
                v00 = fmaxf(v00, 0.f); v01 = fmaxf(v01, 0.f);
                v10 = fmaxf(v10, 0.f); v11 = fmaxf(v11, 0.f);
            }
            if (EPI == 2) {
                float2 e0 = *(const float2*)&res[(size_t)r0 * N + cc];
                float2 e1 = *(const float2*)&res[(size_t)r1 * N + cc];
                v00 += e0.x; v01 += e0.y; v10 += e1.x; v11 += e1.y;
            }
            if (OUTH) {
                __half* Ch = (__half*)Cout + (size_t)z * sC;
                *(__half2*)&Ch[(size_t)r0 * N + cc] = __floats2half2_rn(v00, v01);
                *(__half2*)&Ch[(size_t)r1 * N + cc] = __floats2half2_rn(v10, v11);
            } else {
                float* Cf = (float*)Cout + (size_t)z * sC;
                *(float2*)&Cf[(size_t)r0 * N + cc] = make_float2(v00, v01);
                *(float2*)&Cf[(size_t)r1 * N + cc] = make_float2(v10, v11);
            }
        }
    }
}

// fp16 flash attention; qkv now half. Scale folded into S post-MMA.
__global__ __launch_bounds__(256, 2) void attn_f16_kernel(const __half* __restrict__ qkv,
                                                          __half* __restrict__ aout) {
    __shared__ __half Ks[64][72];
    __shared__ __half Vt[64][72];
    const int bh = blockIdx.y, b = bh >> 4, h = bh & 15;
    const int tid = threadIdx.x, lane = tid & 31, w = tid >> 5;
    const int tg = lane >> 2, tq = lane & 3;
    const int q0 = blockIdx.x * 128 + w * 16;
    const __half* qbase = qkv + (size_t)b * TSEQ * 3072 + h * 64;

    uint32_t qa[4][4];
    {
        const __half* qr0 = qbase + (size_t)(q0 + tg) * 3072;
        const __half* qr1 = qbase + (size_t)(q0 + tg + 8) * 3072;
#pragma unroll
        for (int kc = 0; kc < 4; kc++) {
            int d0 = kc * 16 + 2 * tq;
            qa[kc][0] = *(const uint32_t*)(qr0 + d0);
            qa[kc][1] = *(const uint32_t*)(qr1 + d0);
            qa[kc][2] = *(const uint32_t*)(qr0 + d0 + 8);
            qa[kc][3] = *(const uint32_t*)(qr1 + d0 + 8);
        }
    }
    float oacc[8][4];
#pragma unroll
    for (int dt = 0; dt < 8; dt++)
#pragma unroll
        for (int i = 0; i < 4; i++) oacc[dt][i] = 0.f;
    float m0 = -1e30f, m1 = -1e30f, l0 = 0.f, l1 = 0.f;
    const __half* kbase = qbase + 1024;
    const __half* vbase = qbase + 2048;

    for (int s0 = 0; s0 < TSEQ; s0 += 64) {
        __syncthreads();
        for (int i = tid; i < 64 * 8; i += 256) {
            int j = i >> 3, dv = (i & 7) << 3;
            uint4 kv = *(const uint4*)(kbase + (size_t)(s0 + j) * 3072 + dv);
            uint4 vv = *(const uint4*)(vbase + (size_t)(s0 + j) * 3072 + dv);
            *(uint4*)&Ks[j][dv] = kv;
            const __half* vh = (const __half*)&vv;
#pragma unroll
            for (int q = 0; q < 8; q++) Vt[dv + q][j] = vh[q];
        }
        __syncthreads();

        float s[8][4];
#pragma unroll
        for (int nt = 0; nt < 8; nt++) {
            s[nt][0] = s[nt][1] = s[nt][2] = s[nt][3] = 0.f;
#pragma unroll
            for (int kc = 0; kc < 4; kc++) {
                uint32_t bb[2] = {*(const uint32_t*)&Ks[nt * 8 + tg][kc * 16 + 2 * tq],
                                  *(const uint32_t*)&Ks[nt * 8 + tg][kc * 16 + 8 + 2 * tq]};
                mma_f16(s[nt], qa[kc], bb);
            }
            s[nt][0] *= 0.125f; s[nt][1] *= 0.125f;
            s[nt][2] *= 0.125f; s[nt][3] *= 0.125f;
        }
        float rm0 = -1e30f, rm1 = -1e30f;
#pragma unroll
        for (int nt = 0; nt < 8; nt++) {
            rm0 = fmaxf(rm0, fmaxf(s[nt][0], s[nt][1]));
            rm1 = fmaxf(rm1, fmaxf(s[nt][2], s[nt][3]));
        }
        rm0 = fmaxf(rm0, __shfl_xor_sync(~0u, rm0, 1));
        rm0 = fmaxf(rm0, __shfl_xor_sync(~0u, rm0, 2));
        rm1 = fmaxf(rm1, __shfl_xor_sync(~0u, rm1, 1));
        rm1 = fmaxf(rm1, __shfl_xor_sync(~0u, rm1, 2));
        float mn0 = fmaxf(m0, rm0), mn1 = fmaxf(m1, rm1);
        float sc0 = __expf(m0 - mn0), sc1 = __expf(m1 - mn1);
        m0 = mn0; m1 = mn1;
        float rs0 = 0.f, rs1 = 0.f;
#pragma unroll
        for (int nt = 0; nt < 8; nt++) {
            s[nt][0] = __expf(s[nt][0] - mn0); s[nt][1] = __expf(s[nt][1] - mn0);
            s[nt][2] = __expf(s[nt][2] - mn1); s[nt][3] = __expf(s[nt][3] - mn1);
            rs0 += s[nt][0] + s[nt][1]; rs1 += s[nt][2] + s[nt][3];
        }
        rs0 += __shfl_xor_sync(~0u, rs0, 1); rs0 += __shfl_xor_sync(~0u, rs0, 2);
        rs1 += __shfl_xor_sync(~0u, rs1, 1); rs1 += __shfl_xor_sync(~0u, rs1, 2);
        l0 = l0 * sc0 + rs0; l1 = l1 * sc1 + rs1;
#pragma unroll
        for (int dt = 0; dt < 8; dt++) {
            oacc[dt][0] *= sc0; oacc[dt][1] *= sc0;
            oacc[dt][2] *= sc1; oacc[dt][3] *= sc1;
        }
#pragma unroll
        for (int c = 0; c < 4; c++) {
            uint32_t pa[4];
            pa[0] = packh2(s[2 * c][0],     s[2 * c][1]);
            pa[1] = packh2(s[2 * c][2],     s[2 * c][3]);
            pa[2] = packh2(s[2 * c + 1][0], s[2 * c + 1][1]);
            pa[3] = packh2(s[2 * c + 1][2], s[2 * c + 1][3]);
#pragma unroll
            for (int dt = 0; dt < 8; dt++) {
                uint32_t bb[2] = {*(const uint32_t*)&Vt[dt * 8 + tg][c * 16 + 2 * tq],
                                  *(const uint32_t*)&Vt[dt * 8 + tg][c * 16 + 8 + 2 * tq]};
                mma_f16(oacc[dt], pa, bb);
            }
        }
    }
    float inv0 = 1.f / l0, inv1 = 1.f / l1;
    __half* ab = aout + (size_t)b * TSEQ * CDIM;
    int t0 = q0 + tg, t1 = t0 + 8;
    int c0 = h * 64 + (t0 >> 5), r0b = (t0 & 31) * 64;
    int c1 = h * 64 + (t1 >> 5), r1b = (t1 & 31) * 64;
#pragma unroll
    for (int dt = 0; dt < 8; dt++) {
        int dd = dt * 8 + tq * 2;
        ab[(size_t)(r0b + dd) * CDIM + c0]     = __float2half(oacc[dt][0] * inv0);
        ab[(size_t)(r0b + dd + 1) * CDIM + c0] = __float2half(oacc[dt][1] * inv0);
        ab[(size_t)(r1b + dd) * CDIM + c1]     = __float2half(oacc[dt][2] * inv1);
        ab[(size_t)(r1b + dd + 1) * CDIM + c1] = __float2half(oacc[dt][3] * inv1);
    }
}

__global__ __launch_bounds__(256) void route_kernel(const float* __restrict__ wr,
                                                    const float* __restrict__ br,
                                                    const float* __restrict__ wn,
                                                    const float* __restrict__ bn) {
    int warp = threadIdx.x >> 5, lane = threadIdx.x & 31;
    int n = blockIdx.x * 8 + warp;
    const float* hp = g_h2 + (size_t)n * CDIM;
    float pr[8], pn[8];
#pragma unroll
    for (int e = 0; e < 8; e++) { pr[e] = 0.f; pn[e] = 0.f; }
    for (int c = lane; c < CDIM; c += 32) {
        float hv = hp[c];
#pragma unroll
        for (int e = 0; e < 8; e++) {
            pr[e] += hv * wr[c * 8 + e];
            pn[e] += hv * wn[c * 8 + e];
        }
    }
#pragma unroll
    for (int e = 0; e < 8; e++)
        for (int o = 16; o; o >>= 1) {
            pr[e] += __shfl_xor_sync(~0u, pr[e], o);
            pn[e] += __shfl_xor_sync(~0u, pn[e], o);
        }
    if (lane == 0)
#pragma unroll
        for (int e = 0; e < 8; e++) {
            g_logits[n * 8 + e]  = pr[e] + br[e];
            g_nlogits[n * 8 + e] = pn[e] + bn[e];
        }
}

__global__ __launch_bounds__(256) void route_post_kernel(const float* __restrict__ noise) {
    __shared__ float red[8];
    int n = blockIdx.x * blockDim.x + threadIdx.x;
    float noisy[8], mx = -1e30f;
#pragma unroll
    for (int e = 0; e < 8; e++) {
        float nl = g_nlogits[n * 8 + e];
        float sp = log1pf(expf(-fabsf(nl))) + fmaxf(nl, 0.f);
        float v = g_logits[n * 8 + e] + noise[n * 8 + e] * sp;
        noisy[e] = v; mx = fmaxf(mx, v);
    }
    float s = 0.f, p[8];
#pragma unroll
    for (int e = 0; e < 8; e++) { p[e] = expf(noisy[e] - mx); s += p[e]; }
    float inv = 1.f / s, ent = 0.f;
#pragma unroll
    for (int e = 0; e < 8; e++) { float pe = p[e] * inv; ent -= pe * logf(pe + 1e-8f); }
    int i0 = 0;
#pragma unroll
    for (int e = 1; e < 8; e++) if (noisy[e] > noisy[i0]) i0 = e;
    int i1 = (i0 == 0) ? 1 : 0;
#pragma unroll
    for (int e = 0; e < 8; e++) if (e != i0 && noisy[e] > noisy[i1]) i1 = e;
    float dgl = expf(noisy[i1] - noisy[i0]);
    float g0 = 1.f / (1.f + dgl), g1 = dgl * g0;
    g_sel[n] = i0 | (i1 << 8);
    g_gate[2 * n] = g0; g_gate[2 * n + 1] = g1;
    float es = ent;
    for (int o = 16; o; o >>= 1) es += __shfl_xor_sync(~0u, es, o);
    int lane = threadIdx.x & 31, wid = threadIdx.x >> 5;
    if (lane == 0) red[wid] = es;
    __syncthreads();
    if (threadIdx.x < 8) {
        float t = red[threadIdx.x];
        for (int o = 4; o; o >>= 1) t += __shfl_xor_sync(0xffu, t, o);
        if (threadIdx.x == 0) atomicAdd(&g_ent, t);
    }
}

// capacity assignment + token->slot map
__global__ void assign_kernel() {
    int lane = threadIdx.x;
    int cnt[8];
#pragma unroll
    for (int e = 0; e < 8; e++) cnt[e] = 0;
    unsigned lt = (1u << lane) - 1u;
    for (int n0 = 0; n0 < NTOK; n0 += 32) {
        int n = n0 + lane;
        int sel = g_sel[n];
        int e0 = sel & 255, e1 = (sel >> 8) & 255;
        int s0 = -1, s1 = -1;
#pragma unroll
        for (int e = 0; e < 8; e++) {
            bool mt = (e0 == e) || (e1 == e);
            unsigned mask = __ballot_sync(~0u, mt);
            if (mt) {
                int r = cnt[e] + __popc(mask & lt);
                if (r < CAP) {
                    g_slot_idx[e * CAP + r] = n;
                    if (e0 == e) s0 = e * CAP + r; else s1 = e * CAP + r;
                }
            }
            cnt[e] += __popc(mask);
        }
        g_tok_slot[2 * n]     = s0;
        g_tok_slot[2 * n + 1] = s1;
    }
#pragma unroll
    for (int e = 0; e < 8; e++)
        for (int r = cnt[e] + lane; r < CAP; r += 32)
            g_slot_idx[e * CAP + r] = -1;
}

// out = x2 + g0*yo[s0] + g1*yo[s1] ; tail = entropy/N
__global__ __launch_bounds__(256) void final_kernel(float* __restrict__ out, int out_size) {
    int idx = blockIdx.x * 256 + threadIdx.x;     // over NTOK*256
    int n = idx >> 8, c4 = (idx & 255) << 2;
    float4 acc = *(const float4*)&g_x2[(size_t)n * CDIM + c4];
    int s0 = g_tok_slot[2 * n], s1 = g_tok_slot[2 * n + 1];
    if (s0 >= 0) {
        float g = g_gate[2 * n];
        __half2 a = *(const __half2*)&g_yo[(size_t)s0 * CDIM + c4];
        __half2 bq = *(const __half2*)&g_yo[(size_t)s0 * CDIM + c4 + 2];
        float2 fa = __half22float2(a), fb = __half22float2(bq);
        acc.x += g * fa.x; acc.y += g * fa.y; acc.z += g * fb.x; acc.w += g * fb.y;
    }
    if (s1 >= 0) {
        float g = g_gate[2 * n + 1];
        __half2 a = *(const __half2*)&g_yo[(size_t)s1 * CDIM + c4];
        __half2 bq = *(const __half2*)&g_yo[(size_t)s1 * CDIM + c4 + 2];
        float2 fa = __half22float2(a), fb = __half22float2(bq);
        acc.x += g * fa.x; acc.y += g * fa.y; acc.z += g * fb.x; acc.w += g * fb.y;
    }
    *(float4*)&out[(size_t)n * CDIM + c4] = acc;
    if (idx == 0)
        for (int j = NTOK * CDIM; j < out_size; j++) out[j] = g_ent * (1.f / NTOK);
}

static void* symp(const void* s) { void* p = nullptr; cudaGetSymbolAddress(&p, s); return p; }

extern "C" void kernel_launch(void* const* d_in, const int* in_sizes, int n_in,
                              void* d_out, int out_size) {
    const float* x       = (const float*)d_in[0];
    const float* noise   = (const float*)d_in[1];
    const float* gamma1  = (const float*)d_in[2];
    const float* beta1   = (const float*)d_in[3];
    const float* gamma2  = (const float*)d_in[4];
    const float* beta2   = (const float*)d_in[5];
    const float* w_qkv   = (const float*)d_in[6];
    const float* w_out   = (const float*)d_in[7];
    const float* w_route = (const float*)d_in[8];
    const float* b_route = (const float*)d_in[9];
    const float* w_noise = (const float*)d_in[10];
    const float* b_noise = (const float*)d_in[11];
    const float* w1      = (const float*)d_in[12];
    const float* b1      = (const float*)d_in[13];
    const float* w2      = (const float*)d_in[14];
    const float* b2      = (const float*)d_in[15];
    float* out = (float*)d_out;

    __half*  p_h1h   = (__half*)symp(g_h1h);
    __half*  p_qkvh  = (__half*)symp(g_qkvh);
    __half*  p_attnh = (__half*)symp(g_attnh);
    float*   p_x2    = (float*)symp(g_x2);
    float*   p_h2    = (float*)symp(g_h2);
    __half*  p_h2h   = (__half*)symp(g_h2h);
    __half*  p_hidh  = (__half*)symp(g_hidh);
    __half*  p_yo    = (__half*)symp(g_yo);
    __half*  p_zeroh = (__half*)symp(g_zeroh);
    __half2* p_wqkvh = (__half2*)symp(g_wqkvh);
    __half2* p_wouth = (__half2*)symp(g_wouth);
    __half2* p_w1h   = (__half2*)symp(g_w1h);
    __half2* p_w2h   = (__half2*)symp(g_w2h);
    int*     p_sidx  = (int*)symp(g_slot_idx);

    static int smem_set = 0;
    if (!smem_set) {
        cudaFuncSetAttribute(tgemm4_kernel<0, false, true >, cudaFuncAttributeMaxDynamicSharedMemorySize, SMEM4_BYTES);
        cudaFuncSetAttribute(tgemm4_kernel<2, false, false>, cudaFuncAttributeMaxDynamicSharedMemorySize, SMEM4_BYTES);
        cudaFuncSetAttribute(tgemm4_kernel<1, true,  true >, cudaFuncAttributeMaxDynamicSharedMemorySize, SMEM4_BYTES);
        smem_set = 1;
    }

    zero_kernel<<<1, 256>>>();
    convw_kernel<<<dim3(512 * 3072 / 4 / 256, 1, 1), 256>>>(w_qkv, p_wqkvh, 512, 3072);
    convw_kernel<<<dim3(512 * 1024 / 4 / 256, 1, 1), 256>>>(w_out, p_wouth, 512, 1024);
    convw_kernel<<<dim3(512 * DFF / 4 / 256, 1, NEXP), 256>>>(w1, p_w1h, 512, DFF);
    convw_kernel<<<dim3(2048 * CDIM / 4 / 256, 1, NEXP), 256>>>(w2, p_w2h, 2048, CDIM);

    ln_kernel<<<NTOK, 256>>>(x, gamma1, beta1, nullptr, p_h1h);
    // qkv (half out)
    tgemm4_kernel<0, false, true><<<dim3(3072 / 128, 4096 / 128, 1), 256, SMEM4_BYTES>>>(
        p_h1h, p_wqkvh, p_qkvh, 4096, 3072, 1024,
        nullptr, nullptr, nullptr, p_zeroh, 0, 0, 0, 0);
    attn_f16_kernel<<<dim3(TSEQ / 128, BSZ * 16), 256>>>(p_qkvh, p_attnh);
    // x2 = x + attn @ w_out
    tgemm4_kernel<2, false, false><<<dim3(1024 / 128, 4096 / 128, 1), 256, SMEM4_BYTES>>>(
        p_attnh, p_wouth, p_x2, 4096, 1024, 1024,
        nullptr, x, nullptr, p_zeroh, 0, 0, 0, 0);
    ln_kernel<<<NTOK, 256>>>(p_x2, gamma2, beta2, p_h2, p_h2h);
    route_kernel<<<NTOK / 8, 256>>>(w_route, b_route, w_noise, b_noise);
    route_post_kernel<<<NTOK / 256, 256>>>(noise);
    assign_kernel<<<1, 32>>>();
    // hid = relu(h2[slot] @ w1 + b1), fused gather, half out
    tgemm4_kernel<1, true, true><<<dim3(DFF / 128, 1024 / 128, NEXP), 256, SMEM4_BYTES>>>(
        p_h2h, p_w1h, p_hidh, 1024, DFF, 1024,
        b1, nullptr, p_sidx, p_zeroh,
        0, (size_t)512 * DFF, (size_t)CAP * DFF, DFF);
    // yo[slot] = hid @ w2 + b2 (half out, no gate — applied at gather)
    tgemm4_kernel<0, false, true><<<dim3(CDIM / 128, CAP / 128, NEXP), 256, SMEM4_BYTES>>>(
        p_hidh, p_w2h, p_yo, CAP, CDIM, DFF,
        b2, nullptr, nullptr, p_zeroh,
        (size_t)CAP * DFF, (size_t)2048 * CDIM, (size_t)CAP * CDIM, CDIM);
    final_kernel<<<NTOK, 256>>>(out, out_size);
}